// round 15
// baseline (speedup 1.0000x reference)
#include <cuda_runtime.h>
#include <cuda_fp16.h>
#include <cstdint>

#define EPS 1e-5f

// ---------------- device scratch ----------------
static __device__ float d_feat[2 * 400 * 128];            // feat[b][s][c]
static __device__ float d_Ag[800 * 384];                  // per-n: A'(128), g0(128), g1(128)
static __device__ int   d_chs[800 * 2];                   // per-n: c0, c1
static __device__ __align__(16) uint32_t d_wr2p[592 * 128]; // fp16 A-frags (72 kt x 8 mt) + 2kt pad
static __device__ float d_scores[800 * 400];              // scores[n][s]
static __device__ float d_att[800 * 128];                 // att[b*400+i][c]

#define ROWU2 268   // uint2 row stride: q-stride 536 words % 32 = 24 -> conflict-free

__device__ __forceinline__ float siluf(float y) {
    return y * __fdividef(1.0f, 1.0f + __expf(-y));
}
__device__ __forceinline__ void mma16(float* c, uint32_t a0, uint32_t a1,
                                      uint32_t a2, uint32_t a3,
                                      uint32_t b0, uint32_t b1) {
    asm volatile(
        "mma.sync.aligned.m16n8k16.row.col.f32.f16.f16.f32 "
        "{%0,%1,%2,%3}, {%4,%5,%6,%7}, {%8,%9}, {%0,%1,%2,%3};"
        : "+f"(c[0]), "+f"(c[1]), "+f"(c[2]), "+f"(c[3])
        : "r"(a0), "r"(a1), "r"(a2), "r"(a3), "r"(b0), "r"(b1));
}
__device__ __forceinline__ uint32_t h2u(__half2 h) {
    return *reinterpret_cast<uint32_t*>(&h);
}

// ---- K1 (+pack): feat = SiLU(BN(conv1x1(x,w1))); blocks >= 40 pack wr2 A-frags ----
__global__ void k_feat(const float* __restrict__ x, const float* __restrict__ w1,
                       const float* __restrict__ g1, const float* __restrict__ b1,
                       const float* __restrict__ m1, const float* __restrict__ v1,
                       const float* __restrict__ wr2) {
    int tid = threadIdx.x;
    if (blockIdx.x >= 40) {
        int sub = tid >> 5, lane = tid & 31;
        int blk = (blockIdx.x - 40) * 16 + sub;     // 0..575 (36 blocks x 16 warps)
        if (blk < 576) {
            int mt = blk & 7, kt = blk >> 3;
            int ict = kt & 7, tap = kt >> 3;
            int g = lane >> 2, q = lane & 3;
            int oc = mt * 16 + g;
            int ic0 = ict * 16 + 2 * q;
            #define WV(o, i) wr2[(o) * 1152 + (i) * 9 + tap]
            uint32_t r0 = h2u(__floats2half2_rn(WV(oc,     ic0),     WV(oc,     ic0 + 1)));
            uint32_t r1 = h2u(__floats2half2_rn(WV(oc + 8, ic0),     WV(oc + 8, ic0 + 1)));
            uint32_t r2 = h2u(__floats2half2_rn(WV(oc,     ic0 + 8), WV(oc,     ic0 + 9)));
            uint32_t r3 = h2u(__floats2half2_rn(WV(oc + 8, ic0 + 8), WV(oc + 8, ic0 + 9)));
            #undef WV
            uint32_t* dst = d_wr2p + (blk * 32 + lane) * 4;
            dst[0] = r0; dst[1] = r1; dst[2] = r2; dst[3] = r3;
        }
        return;
    }
    extern __shared__ float sm[];
    float* w1s = sm;               // 128*129
    float* xs  = sm + 128 * 129;   // 128*20
    int bb = blockIdx.x / 20, h = blockIdx.x % 20;
    for (int idx = tid; idx < 128 * 128; idx += 512) {
        int oc = idx >> 7, ic = idx & 127;
        w1s[oc * 129 + ic] = w1[idx];
    }
    for (int idx = tid; idx < 2560; idx += 512) {
        int ic = idx / 20, w = idx % 20;
        xs[idx] = x[(bb * 128 + ic) * 400 + h * 20 + w];
    }
    __syncthreads();
    int c = tid & 127, wh = tid >> 7;   // wh: 0..3
    float sc = g1[c] * rsqrtf(v1[c] + EPS);
    float bi = b1[c] - m1[c] * sc;
    for (int w = wh * 5; w < wh * 5 + 5; ++w) {
        float acc = 0.f;
#pragma unroll 8
        for (int ic = 0; ic < 128; ++ic) acc += w1s[c * 129 + ic] * xs[ic * 20 + w];
        d_feat[(bb * 400 + h * 20 + w) * 128 + c] = siluf(acc * sc + bi);
    }
}

// ---- K2: per-n decomposition of permuted r1 conv; smem-staged gather, 2 n in flight ----
__global__ void k_prep(const float* __restrict__ wr1,
                       const float* __restrict__ gr1, const float* __restrict__ br1,
                       const float* __restrict__ mr1, const float* __restrict__ vr1) {
    extern __shared__ float sm[];
    float* wr1s = sm;               // 128*257
    float* G    = sm + 128 * 257;   // 2 x 260
    int tid = threadIdx.x;          // 256 threads
    for (int idx = tid; idx < 128 * 256; idx += 256) {
        int oc2 = idx >> 8, cp = idx & 255;
        wr1s[oc2 * 257 + cp] = wr1[idx];
    }
    __syncthreads();
    int p = tid >> 7, ocl = tid & 127;
    float sc = gr1[ocl] * rsqrtf(vr1[ocl] + EPS);
    float bi = br1[ocl] - mr1[ocl] * sc;
    for (int ni = 0; ni < 2; ++ni) {
        int n = blockIdx.x * 4 + ni * 2 + p;
        int b = n / 400, m = n % 400;
        int u0 = m * 256;
        int k0 = u0 / 400, r0 = u0 - k0 * 400;
        int split = 400 - r0; if (split > 256) split = 256;
        bool r1A = (k0 < 128), r2A = (k0 + 1 < 128);
        const float* fb = d_feat + b * 400 * 128;
        for (int cp = ocl; cp < 256; cp += 128) {
            float v = 0.f;
            if (cp < split) { if (r1A) v = fb[(r0 + cp) * 128 + k0]; }
            else            { if (r2A) v = fb[(r0 + cp - 400) * 128 + (k0 + 1)]; }
            G[p * 260 + cp] = v;
        }
        __syncthreads();
        const float* wrow = wr1s + ocl * 257;
        const float* Gp = G + p * 260;
        float A = 0.f, s1 = 0.f, s2 = 0.f;
        if (r1A) {
#pragma unroll 4
            for (int cp = 0; cp < split; ++cp) A += wrow[cp] * Gp[cp];
        } else {
#pragma unroll 4
            for (int cp = 0; cp < split; ++cp) s1 += wrow[cp];
        }
        if (r2A) {
#pragma unroll 4
            for (int cp = split; cp < 256; ++cp) A += wrow[cp] * Gp[cp];
        } else {
#pragma unroll 4
            for (int cp = split; cp < 256; ++cp) s2 += wrow[cp];
        }
        d_Ag[n * 384 + ocl]       = A * sc + bi;
        d_Ag[n * 384 + 128 + ocl] = s1 * sc;
        d_Ag[n * 384 + 256 + ocl] = s2 * sc;
        if (ocl == 0) {
            int c0 = k0 - 128;     if (c0 < 0) c0 = 0; if (c0 > 127) c0 = 127;
            int c1 = k0 + 1 - 128; if (c1 < 0) c1 = 0; if (c1 > 127) c1 = 127;
            d_chs[n * 2] = c0; d_chs[n * 2 + 1] = c1;
        }
        __syncthreads();
    }
}

// ---- K3: fused r1act -> 3x3 fp16 mma conv -> BN+SiLU -> r3 -> BN+SiLU -> scores ----
// 640 threads = 4 mwg (M=32) x 5 ng. A prefetch distance 2 (even/odd); B batched per phase.
__global__ void __launch_bounds__(640, 1)
k_rel(const float* __restrict__ gr2, const float* __restrict__ br2,
      const float* __restrict__ mr2, const float* __restrict__ vr2,
      const float* __restrict__ wr3,
      const float* __restrict__ gr3, const float* __restrict__ br3,
      const float* __restrict__ mr3, const float* __restrict__ vr3) {
    extern __shared__ uint32_t smw[];
    uint32_t* tileW = smw;                       // 32*ROWU2*2 words
    float* f0t   = (float*)(smw + 32 * ROWU2 * 2);
    float* f1t   = f0t + 264;
    float* AgS   = f1t + 264;                    // 384
    float* spart = AgS + 384;                    // 800
    float* epar  = spart + 800;                  // 384: sc2, bi2, w3

    int n = blockIdx.x >> 1, half = blockIdx.x & 1;
    int b = n / 400;
    int tid = threadIdx.x;
    int c0 = d_chs[n * 2], c1 = d_chs[n * 2 + 1];

    // epilogue params into smem (overlaps with feat/Ag gathers)
    if (tid >= 384 && tid < 512) {
        int cc = tid - 384;
        float s2 = gr2[cc] * rsqrtf(vr2[cc] + EPS);
        epar[cc] = s2;
        epar[128 + cc] = br2[cc] - mr2[cc] * s2;
        epar[256 + cc] = wr3[cc];
    }
    for (int idx = tid; idx < 384; idx += 640) AgS[idx] = d_Ag[n * 384 + idx];
    if (tid < 264) {
        int tr = tid / 22, tc = tid % 22;
        int h = half * 10 + tr - 1, w = tc - 1;
        float v0 = 0.f, v1v = 0.f;
        if (h >= 0 && h < 20 && w >= 0 && w < 20) {
            int s = h * 20 + w;
            v0  = d_feat[(b * 400 + s) * 128 + c0];
            v1v = d_feat[(b * 400 + s) * 128 + c1];
        }
        f0t[tid] = v0; f1t[tid] = v1v;
    }
    __syncthreads();

    // fill r1act tile as fp16 pairs: fixed (icp, row) per thread, zero div/mod in loop
    {
        int icp = tid & 63;            // 0..63
        int t = tid >> 6;              // 0..9
        int ic = icp * 2;
        float a0 = AgS[ic],     g00 = AgS[128 + ic],     g10 = AgS[256 + ic];
        float a1 = AgS[ic + 1], g01 = AgS[128 + ic + 1], g11 = AgS[256 + ic + 1];
        int q = icp & 3, word = (icp >> 2) & 1, ict = icp >> 3;
        uint32_t* dbase = tileW + ((ict * 4 + q) * ROWU2) * 2 + word;
#pragma unroll
        for (int rep = 0; rep < 2; ++rep) {
            int tr = t + rep * 10;
            if (rep == 1 && t >= 2) break;     // rows 10,11 handled by t<2
            int h = half * 10 + tr - 1;
            bool hok = (h >= 0 && h < 20);
            const float* f0p = f0t + tr * 22;
            const float* f1p = f1t + tr * 22;
            uint32_t* dst = dbase + tr * 44;
#pragma unroll
            for (int tc = 0; tc < 22; ++tc) {
                float y0 = 0.f, y1 = 0.f;
                if (hok && tc >= 1 && tc <= 20) {
                    float f0 = f0p[tc], f1 = f1p[tc];
                    y0 = siluf(a0 + g00 * f0 + g10 * f1);
                    y1 = siluf(a1 + g01 * f0 + g11 * f1);
                }
                dst[tc * 2] = h2u(__floats2half2_rn(y0, y1));
            }
        }
    }
    __syncthreads();

    // ---- implicit-GEMM mainloop: tap outer (9), ict unroll-2 (4 double-phases) ----
    int warp = tid >> 5, lane = tid & 31;
    int mwg = warp & 3, ng = warp >> 2;        // ng: 0..4
    int q = lane & 3, g = lane >> 2;

    int coffb[5];
#pragma unroll
    for (int nt = 0; nt < 5; ++nt) {
        int s = (ng * 5 + nt) * 8 + g;
        int r = s / 20, w = s % 20;
        coffb[nt] = (r * 22 + w) * 8;
    }
    float acc0[5][4], acc1[5][4];
#pragma unroll
    for (int nt = 0; nt < 5; ++nt)
#pragma unroll
        for (int r = 0; r < 4; ++r) { acc0[nt][r] = 0.f; acc1[nt][r] = 0.f; }

    const char* tbq = (const char*)tileW + q * (ROWU2 * 8);   // q folded in
    const int ROWB = 4 * ROWU2 * 8;            // bytes between consecutive ict rows
    int mt0 = mwg * 2, mt1 = mt0 + 1;
    const uint4* Aq0 = (const uint4*)d_wr2p + mt0 * 32 + lane;
    const uint4* Aq1 = (const uint4*)d_wr2p + mt1 * 32 + lane;

    uint4 aE0 = Aq0[0],   aE1 = Aq1[0];        // kt 0
    uint4 aO0 = Aq0[256], aO1 = Aq1[256];      // kt 1
    Aq0 += 512; Aq1 += 512;                    // next prefetch target: kt 2
    for (int tap = 0; tap < 9; ++tap) {
        const char* tbase = tbq + ((tap / 3) * 22 + (tap % 3)) * 8;
#pragma unroll
        for (int i2 = 0; i2 < 4; ++i2) {
            {   // even kt phase
                const char* trow = tbase + (2 * i2) * ROWB;
                uint2 bbf[5];
#pragma unroll
                for (int nt = 0; nt < 5; ++nt)
                    bbf[nt] = *(const uint2*)(trow + coffb[nt]);
#pragma unroll
                for (int nt = 0; nt < 5; ++nt) {
                    mma16(acc0[nt], aE0.x, aE0.y, aE0.z, aE0.w, bbf[nt].x, bbf[nt].y);
                    mma16(acc1[nt], aE1.x, aE1.y, aE1.z, aE1.w, bbf[nt].x, bbf[nt].y);
                }
                aE0 = *Aq0; Aq0 += 256;        // prefetch kt+2 (even)
                aE1 = *Aq1; Aq1 += 256;
            }
            {   // odd kt phase
                const char* trow = tbase + (2 * i2 + 1) * ROWB;
                uint2 bbf[5];
#pragma unroll
                for (int nt = 0; nt < 5; ++nt)
                    bbf[nt] = *(const uint2*)(trow + coffb[nt]);
#pragma unroll
                for (int nt = 0; nt < 5; ++nt) {
                    mma16(acc0[nt], aO0.x, aO0.y, aO0.z, aO0.w, bbf[nt].x, bbf[nt].y);
                    mma16(acc1[nt], aO1.x, aO1.y, aO1.z, aO1.w, bbf[nt].x, bbf[nt].y);
                }
                aO0 = *Aq0; Aq0 += 256;        // prefetch kt+2 (odd)
                aO1 = *Aq1; Aq1 += 256;
            }
        }
    }

    // ---- epilogue: BN2+SiLU, r3 dot, cross-lane + cross-warp reduce ----
    int ocA = mwg * 32 + g, ocB = ocA + 8, ocC = ocA + 16, ocD = ocA + 24;
    float scA = epar[ocA], biA = epar[128 + ocA], w3A = epar[256 + ocA];
    float scB = epar[ocB], biB = epar[128 + ocB], w3B = epar[256 + ocB];
    float scC = epar[ocC], biC = epar[128 + ocC], w3C = epar[256 + ocC];
    float scD = epar[ocD], biD = epar[128 + ocD], w3D = epar[256 + ocD];

#pragma unroll
    for (int nt = 0; nt < 5; ++nt) {
#pragma unroll
        for (int reg = 0; reg < 2; ++reg) {
            float v = w3A * siluf(scA * acc0[nt][reg]     + biA)
                    + w3B * siluf(scB * acc0[nt][reg + 2] + biB)
                    + w3C * siluf(scC * acc1[nt][reg]     + biC)
                    + w3D * siluf(scD * acc1[nt][reg + 2] + biD);
            v += __shfl_xor_sync(0xffffffffu, v, 4);
            v += __shfl_xor_sync(0xffffffffu, v, 8);
            v += __shfl_xor_sync(0xffffffffu, v, 16);
            if (g == 0) {
                int s = (ng * 5 + nt) * 8 + 2 * q + reg;
                spart[mwg * 200 + s] = v;
            }
        }
    }
    __syncthreads();
    if (tid < 200) {
        float s4 = spart[tid] + spart[200 + tid] + spart[400 + tid] + spart[600 + tid];
        float sc3 = gr3[0] * rsqrtf(vr3[0] + EPS);
        float bi3 = br3[0] - mr3[0] * sc3;
        d_scores[n * 400 + half * 200 + tid] = siluf(sc3 * s4 + bi3);
    }
}

// ---- K4: att[n][c] = sum_s scores[n][s] * feat[b][s][c]; 2 n/block, 4 s-quarters ----
__global__ void __launch_bounds__(512, 2) k_att() {
    __shared__ float sco[2 * 400];
    __shared__ float part[4][2][128];
    int n0 = blockIdx.x * 2, b = n0 / 400, tid = threadIdx.x;
    for (int i = tid; i < 800; i += 512) sco[i] = d_scores[n0 * 400 + i];
    __syncthreads();
    int c = tid & 127, sq = tid >> 7;      // sq: 0..3
    float a0 = 0.f, a1 = 0.f;
    const float* fb = d_feat + b * 400 * 128;
    int s0 = sq * 100;
#pragma unroll 5
    for (int s = s0; s < s0 + 100; ++s) {
        float f = fb[s * 128 + c];
        a0 += sco[s] * f;
        a1 += sco[400 + s] * f;
    }
    part[sq][0][c] = a0;
    part[sq][1][c] = a1;
    __syncthreads();
    if (tid < 256) {
        int j = tid >> 7, cc = tid & 127;
        float v = part[0][j][cc] + part[1][j][cc] + part[2][j][cc] + part[3][j][cc];
        d_att[(n0 + j) * 128 + cc] = v;
    }
}

// ---- K5: out = SiLU(BN(conv1x1(att, w2))) + x ----
__global__ void k_out(float* __restrict__ out, const float* __restrict__ x,
                      const float* __restrict__ w2,
                      const float* __restrict__ g2, const float* __restrict__ b2,
                      const float* __restrict__ m2, const float* __restrict__ v2) {
    extern __shared__ float sm[];
    float* w2s  = sm;              // 128*129
    float* atts = sm + 128 * 129;  // 20*128
    int bb = blockIdx.x / 20, h = blockIdx.x % 20, tid = threadIdx.x;
    for (int idx = tid; idx < 128 * 128; idx += 512) {
        int oc = idx >> 7, ic = idx & 127;
        w2s[oc * 129 + ic] = w2[idx];
    }
    for (int idx = tid; idx < 2560; idx += 512) {
        int w = idx >> 7, ic = idx & 127;
        atts[idx] = d_att[(bb * 400 + h * 20 + w) * 128 + ic];
    }
    __syncthreads();
    int oc = tid & 127, wh = tid >> 7;   // wh: 0..3
    float sc = g2[oc] * rsqrtf(v2[oc] + EPS);
    float bi = b2[oc] - m2[oc] * sc;
    for (int w = wh * 5; w < wh * 5 + 5; ++w) {
        float acc = 0.f;
#pragma unroll 8
        for (int ic = 0; ic < 128; ++ic) acc += w2s[oc * 129 + ic] * atts[w * 128 + ic];
        float y = acc * sc + bi;
        int gi = (bb * 128 + oc) * 400 + h * 20 + w;
        out[gi] = siluf(y) + x[gi];
    }
}

extern "C" void kernel_launch(void* const* d_in, const int* in_sizes, int n_in,
                              void* d_out, int out_size) {
    const float* x   = (const float*)d_in[0];
    const float* w1  = (const float*)d_in[1];
    const float* g1  = (const float*)d_in[2];
    const float* b1  = (const float*)d_in[3];
    const float* m1  = (const float*)d_in[4];
    const float* v1  = (const float*)d_in[5];
    const float* w2  = (const float*)d_in[6];
    const float* g2  = (const float*)d_in[7];
    const float* b2  = (const float*)d_in[8];
    const float* m2  = (const float*)d_in[9];
    const float* v2  = (const float*)d_in[10];
    const float* wr1 = (const float*)d_in[11];
    const float* gr1 = (const float*)d_in[12];
    const float* br1 = (const float*)d_in[13];
    const float* mr1 = (const float*)d_in[14];
    const float* vr1 = (const float*)d_in[15];
    const float* wr2 = (const float*)d_in[16];
    const float* gr2 = (const float*)d_in[17];
    const float* br2 = (const float*)d_in[18];
    const float* mr2 = (const float*)d_in[19];
    const float* vr2 = (const float*)d_in[20];
    const float* wr3 = (const float*)d_in[21];
    const float* gr3 = (const float*)d_in[22];
    const float* br3 = (const float*)d_in[23];
    const float* mr3 = (const float*)d_in[24];
    const float* vr3 = (const float*)d_in[25];
    float* out = (float*)d_out;

    const int smem_rel  = (32 * ROWU2 * 2 + 264 + 264 + 384 + 800 + 384) * 4;
    const int smem_prep = (128 * 257 + 2 * 260) * 4;

    cudaFuncSetAttribute(k_feat, cudaFuncAttributeMaxDynamicSharedMemorySize, 76288);
    cudaFuncSetAttribute(k_prep, cudaFuncAttributeMaxDynamicSharedMemorySize, smem_prep);
    cudaFuncSetAttribute(k_rel,  cudaFuncAttributeMaxDynamicSharedMemorySize, smem_rel);
    cudaFuncSetAttribute(k_out,  cudaFuncAttributeMaxDynamicSharedMemorySize, 76288);

    k_feat<<<76, 512, 76288>>>(x, w1, g1, b1, m1, v1, wr2);    // blocks 40..75 pack wr2
    k_prep<<<200, 256, smem_prep>>>(wr1, gr1, br1, mr1, vr1);
    k_rel<<<1600, 640, smem_rel>>>(gr2, br2, mr2, vr2, wr3, gr3, br3, mr3, vr3);
    k_att<<<400, 512>>>();
    k_out<<<40, 512, 76288>>>(out, x, w2, g2, b2, m2, v2);
}

// round 16
// speedup vs baseline: 1.0035x; 1.0035x over previous
#include <cuda_runtime.h>
#include <cuda_fp16.h>
#include <cstdint>

#define EPS 1e-5f

// ---------------- device scratch ----------------
static __device__ float d_feat[2 * 400 * 128];            // feat[b][s][c]
static __device__ float d_Ag[800 * 384];                  // per-n: A'(128), g0(128), g1(128)
static __device__ __align__(16) uint32_t d_wr2p[592 * 128]; // fp16 A-frags (72 kt x 8 mt) + 2kt pad
static __device__ float d_scores[800 * 400];              // scores[n][s]
static __device__ float d_att[800 * 128];                 // att[b*400+i][c]

#define ROWU2 268   // uint2 row stride: q-stride 536 words % 32 = 24 -> conflict-free

__device__ __forceinline__ float siluf(float y) {
    return y * __fdividef(1.0f, 1.0f + __expf(-y));
}
__device__ __forceinline__ void mma16(float* c, uint32_t a0, uint32_t a1,
                                      uint32_t a2, uint32_t a3,
                                      uint32_t b0, uint32_t b1) {
    asm volatile(
        "mma.sync.aligned.m16n8k16.row.col.f32.f16.f16.f32 "
        "{%0,%1,%2,%3}, {%4,%5,%6,%7}, {%8,%9}, {%0,%1,%2,%3};"
        : "+f"(c[0]), "+f"(c[1]), "+f"(c[2]), "+f"(c[3])
        : "r"(a0), "r"(a1), "r"(a2), "r"(a3), "r"(b0), "r"(b1));
}
__device__ __forceinline__ uint32_t h2u(__half2 h) {
    return *reinterpret_cast<uint32_t*>(&h);
}

// ---- K1 (+pack): feat = SiLU(BN(conv1x1(x,w1))); blocks >= 40 pack wr2 A-frags ----
__global__ void k_feat(const float* __restrict__ x, const float* __restrict__ w1,
                       const float* __restrict__ g1, const float* __restrict__ b1,
                       const float* __restrict__ m1, const float* __restrict__ v1,
                       const float* __restrict__ wr2) {
    int tid = threadIdx.x;
    if (blockIdx.x >= 40) {
        int sub = tid >> 5, lane = tid & 31;
        int blk = (blockIdx.x - 40) * 16 + sub;     // 0..575 (36 blocks x 16 warps)
        if (blk < 576) {
            int mt = blk & 7, kt = blk >> 3;
            int ict = kt & 7, tap = kt >> 3;
            int g = lane >> 2, q = lane & 3;
            int oc = mt * 16 + g;
            int ic0 = ict * 16 + 2 * q;
            #define WV(o, i) wr2[(o) * 1152 + (i) * 9 + tap]
            uint32_t r0 = h2u(__floats2half2_rn(WV(oc,     ic0),     WV(oc,     ic0 + 1)));
            uint32_t r1 = h2u(__floats2half2_rn(WV(oc + 8, ic0),     WV(oc + 8, ic0 + 1)));
            uint32_t r2 = h2u(__floats2half2_rn(WV(oc,     ic0 + 8), WV(oc,     ic0 + 9)));
            uint32_t r3 = h2u(__floats2half2_rn(WV(oc + 8, ic0 + 8), WV(oc + 8, ic0 + 9)));
            #undef WV
            uint32_t* dst = d_wr2p + (blk * 32 + lane) * 4;
            dst[0] = r0; dst[1] = r1; dst[2] = r2; dst[3] = r3;
        }
        return;
    }
    extern __shared__ float sm[];
    float* w1s = sm;               // 128*129
    float* xs  = sm + 128 * 129;   // 128*20
    int bb = blockIdx.x / 20, h = blockIdx.x % 20;
    for (int idx = tid; idx < 128 * 128; idx += 512) {
        int oc = idx >> 7, ic = idx & 127;
        w1s[oc * 129 + ic] = w1[idx];
    }
    for (int idx = tid; idx < 2560; idx += 512) {
        int ic = idx / 20, w = idx % 20;
        xs[idx] = x[(bb * 128 + ic) * 400 + h * 20 + w];
    }
    __syncthreads();
    int c = tid & 127, wh = tid >> 7;   // wh: 0..3
    float sc = g1[c] * rsqrtf(v1[c] + EPS);
    float bi = b1[c] - m1[c] * sc;
    for (int w = wh * 5; w < wh * 5 + 5; ++w) {
        float acc = 0.f;
#pragma unroll 8
        for (int ic = 0; ic < 128; ++ic) acc += w1s[c * 129 + ic] * xs[ic * 20 + w];
        d_feat[(bb * 400 + h * 20 + w) * 128 + c] = siluf(acc * sc + bi);
    }
}

// ---- K2: per-n decomposition of permuted r1 conv; smem-staged gather, 2 n in flight ----
__global__ void k_prep(const float* __restrict__ wr1,
                       const float* __restrict__ gr1, const float* __restrict__ br1,
                       const float* __restrict__ mr1, const float* __restrict__ vr1) {
    extern __shared__ float sm[];
    float* wr1s = sm;               // 128*257
    float* G    = sm + 128 * 257;   // 2 x 260
    int tid = threadIdx.x;          // 256 threads
    for (int idx = tid; idx < 128 * 256; idx += 256) {
        int oc2 = idx >> 8, cp = idx & 255;
        wr1s[oc2 * 257 + cp] = wr1[idx];
    }
    __syncthreads();
    int p = tid >> 7, ocl = tid & 127;
    float sc = gr1[ocl] * rsqrtf(vr1[ocl] + EPS);
    float bi = br1[ocl] - mr1[ocl] * sc;
    for (int ni = 0; ni < 2; ++ni) {
        int n = blockIdx.x * 4 + ni * 2 + p;
        int b = n / 400, m = n % 400;
        int u0 = m * 256;
        int k0 = u0 / 400, r0 = u0 - k0 * 400;
        int split = 400 - r0; if (split > 256) split = 256;
        bool r1A = (k0 < 128), r2A = (k0 + 1 < 128);
        const float* fb = d_feat + b * 400 * 128;
        for (int cp = ocl; cp < 256; cp += 128) {
            float v = 0.f;
            if (cp < split) { if (r1A) v = fb[(r0 + cp) * 128 + k0]; }
            else            { if (r2A) v = fb[(r0 + cp - 400) * 128 + (k0 + 1)]; }
            G[p * 260 + cp] = v;
        }
        __syncthreads();
        const float* wrow = wr1s + ocl * 257;
        const float* Gp = G + p * 260;
        float A = 0.f, s1 = 0.f, s2 = 0.f;
        if (r1A) {
#pragma unroll 4
            for (int cp = 0; cp < split; ++cp) A += wrow[cp] * Gp[cp];
        } else {
#pragma unroll 4
            for (int cp = 0; cp < split; ++cp) s1 += wrow[cp];
        }
        if (r2A) {
#pragma unroll 4
            for (int cp = split; cp < 256; ++cp) A += wrow[cp] * Gp[cp];
        } else {
#pragma unroll 4
            for (int cp = split; cp < 256; ++cp) s2 += wrow[cp];
        }
        d_Ag[n * 384 + ocl]       = A * sc + bi;
        d_Ag[n * 384 + 128 + ocl] = s1 * sc;
        d_Ag[n * 384 + 256 + ocl] = s2 * sc;
        __syncthreads();
    }
}

// ---- K3: fused r1act -> 3x3 fp16 mma conv -> BN+SiLU -> r3 -> BN+SiLU -> scores ----
// 640 threads = 4 mwg (M=32) x 5 ng. A prefetch distance 2 (even/odd); B batched per phase.
// c0/c1 computed arithmetically; feat gather over 528 threads; initial A LDGs hoisted pre-fill.
__global__ void __launch_bounds__(640, 1)
k_rel(const float* __restrict__ gr2, const float* __restrict__ br2,
      const float* __restrict__ mr2, const float* __restrict__ vr2,
      const float* __restrict__ wr3,
      const float* __restrict__ gr3, const float* __restrict__ br3,
      const float* __restrict__ mr3, const float* __restrict__ vr3) {
    extern __shared__ uint32_t smw[];
    uint32_t* tileW = smw;                       // 32*ROWU2*2 words
    float* f0t   = (float*)(smw + 32 * ROWU2 * 2);
    float* f1t   = f0t + 264;
    float* AgS   = f1t + 264;                    // 384
    float* spart = AgS + 384;                    // 800
    float* epar  = spart + 800;                  // 384: sc2, bi2, w3

    int n = blockIdx.x >> 1, half = blockIdx.x & 1;
    int b = n / 400;
    int m = n - b * 400;
    int tid = threadIdx.x;
    // c0/c1 arithmetic: k0 = (m*256)/400 = (m*16)/25
    int k0 = (m * 16) / 25;
    int c0 = k0 - 128;     if (c0 < 0) c0 = 0; if (c0 > 127) c0 = 127;
    int c1 = k0 + 1 - 128; if (c1 < 0) c1 = 0; if (c1 > 127) c1 = 127;

    // epilogue params into smem (overlaps with feat/Ag gathers)
    if (tid >= 512) {
        int cc = tid - 512;
        float s2 = gr2[cc] * rsqrtf(vr2[cc] + EPS);
        epar[cc] = s2;
        epar[128 + cc] = br2[cc] - mr2[cc] * s2;
        epar[256 + cc] = wr3[cc];
    }
    for (int idx = tid; idx < 384; idx += 640) AgS[idx] = d_Ag[n * 384 + idx];
    if (tid < 528) {
        int j = tid >> 1, sel = tid & 1;
        int tr = j / 22, tc = j % 22;
        int h = half * 10 + tr - 1, w = tc - 1;
        float v = 0.f;
        if (h >= 0 && h < 20 && w >= 0 && w < 20) {
            int s = h * 20 + w;
            v = d_feat[(b * 400 + s) * 128 + (sel ? c1 : c0)];
        }
        (sel ? f1t : f0t)[j] = v;
    }

    // ---- mainloop thread mapping + hoisted initial A loads (hide LDG under fill) ----
    int warp = tid >> 5, lane = tid & 31;
    int mwg = warp & 3, ng = warp >> 2;        // ng: 0..4
    int q = lane & 3, g = lane >> 2;
    int mt0 = mwg * 2, mt1 = mt0 + 1;
    const uint4* Aq0 = (const uint4*)d_wr2p + mt0 * 32 + lane;
    const uint4* Aq1 = (const uint4*)d_wr2p + mt1 * 32 + lane;
    uint4 aE0 = Aq0[0],   aE1 = Aq1[0];        // kt 0
    uint4 aO0 = Aq0[256], aO1 = Aq1[256];      // kt 1
    Aq0 += 512; Aq1 += 512;                    // next prefetch target: kt 2

    __syncthreads();

    // fill r1act tile as fp16 pairs: fixed (icp, row) per thread, zero div/mod in loop
    {
        int icp = tid & 63;            // 0..63
        int t = tid >> 6;              // 0..9
        int ic = icp * 2;
        float a0 = AgS[ic],     g00 = AgS[128 + ic],     g10 = AgS[256 + ic];
        float a1 = AgS[ic + 1], g01 = AgS[128 + ic + 1], g11 = AgS[256 + ic + 1];
        int qf = icp & 3, word = (icp >> 2) & 1, ict = icp >> 3;
        uint32_t* dbase = tileW + ((ict * 4 + qf) * ROWU2) * 2 + word;
#pragma unroll
        for (int rep = 0; rep < 2; ++rep) {
            int tr = t + rep * 10;
            if (rep == 1 && t >= 2) break;     // rows 10,11 handled by t<2
            int h = half * 10 + tr - 1;
            bool hok = (h >= 0 && h < 20);
            const float* f0p = f0t + tr * 22;
            const float* f1p = f1t + tr * 22;
            uint32_t* dst = dbase + tr * 44;
#pragma unroll
            for (int tc = 0; tc < 22; ++tc) {
                float y0 = 0.f, y1 = 0.f;
                if (hok && tc >= 1 && tc <= 20) {
                    float f0 = f0p[tc], f1 = f1p[tc];
                    y0 = siluf(a0 + g00 * f0 + g10 * f1);
                    y1 = siluf(a1 + g01 * f0 + g11 * f1);
                }
                dst[tc * 2] = h2u(__floats2half2_rn(y0, y1));
            }
        }
    }
    __syncthreads();

    // ---- implicit-GEMM mainloop: tap outer (9), ict unroll-2 (4 double-phases) ----
    int coffb[5];
#pragma unroll
    for (int nt = 0; nt < 5; ++nt) {
        int s = (ng * 5 + nt) * 8 + g;
        int r = s / 20, w = s % 20;
        coffb[nt] = (r * 22 + w) * 8;
    }
    float acc0[5][4], acc1[5][4];
#pragma unroll
    for (int nt = 0; nt < 5; ++nt)
#pragma unroll
        for (int r = 0; r < 4; ++r) { acc0[nt][r] = 0.f; acc1[nt][r] = 0.f; }

    const char* tbq = (const char*)tileW + q * (ROWU2 * 8);   // q folded in
    const int ROWB = 4 * ROWU2 * 8;            // bytes between consecutive ict rows
    for (int tap = 0; tap < 9; ++tap) {
        const char* tbase = tbq + ((tap / 3) * 22 + (tap % 3)) * 8;
#pragma unroll
        for (int i2 = 0; i2 < 4; ++i2) {
            {   // even kt phase
                const char* trow = tbase + (2 * i2) * ROWB;
                uint2 bbf[5];
#pragma unroll
                for (int nt = 0; nt < 5; ++nt)
                    bbf[nt] = *(const uint2*)(trow + coffb[nt]);
#pragma unroll
                for (int nt = 0; nt < 5; ++nt) {
                    mma16(acc0[nt], aE0.x, aE0.y, aE0.z, aE0.w, bbf[nt].x, bbf[nt].y);
                    mma16(acc1[nt], aE1.x, aE1.y, aE1.z, aE1.w, bbf[nt].x, bbf[nt].y);
                }
                aE0 = *Aq0; Aq0 += 256;        // prefetch kt+2 (even)
                aE1 = *Aq1; Aq1 += 256;
            }
            {   // odd kt phase
                const char* trow = tbase + (2 * i2 + 1) * ROWB;
                uint2 bbf[5];
#pragma unroll
                for (int nt = 0; nt < 5; ++nt)
                    bbf[nt] = *(const uint2*)(trow + coffb[nt]);
#pragma unroll
                for (int nt = 0; nt < 5; ++nt) {
                    mma16(acc0[nt], aO0.x, aO0.y, aO0.z, aO0.w, bbf[nt].x, bbf[nt].y);
                    mma16(acc1[nt], aO1.x, aO1.y, aO1.z, aO1.w, bbf[nt].x, bbf[nt].y);
                }
                aO0 = *Aq0; Aq0 += 256;        // prefetch kt+2 (odd)
                aO1 = *Aq1; Aq1 += 256;
            }
        }
    }

    // ---- epilogue: BN2+SiLU, r3 dot, cross-lane + cross-warp reduce ----
    int ocA = mwg * 32 + g, ocB = ocA + 8, ocC = ocA + 16, ocD = ocA + 24;
    float scA = epar[ocA], biA = epar[128 + ocA], w3A = epar[256 + ocA];
    float scB = epar[ocB], biB = epar[128 + ocB], w3B = epar[256 + ocB];
    float scC = epar[ocC], biC = epar[128 + ocC], w3C = epar[256 + ocC];
    float scD = epar[ocD], biD = epar[128 + ocD], w3D = epar[256 + ocD];

#pragma unroll
    for (int nt = 0; nt < 5; ++nt) {
#pragma unroll
        for (int reg = 0; reg < 2; ++reg) {
            float v = w3A * siluf(scA * acc0[nt][reg]     + biA)
                    + w3B * siluf(scB * acc0[nt][reg + 2] + biB)
                    + w3C * siluf(scC * acc1[nt][reg]     + biC)
                    + w3D * siluf(scD * acc1[nt][reg + 2] + biD);
            v += __shfl_xor_sync(0xffffffffu, v, 4);
            v += __shfl_xor_sync(0xffffffffu, v, 8);
            v += __shfl_xor_sync(0xffffffffu, v, 16);
            if (g == 0) {
                int s = (ng * 5 + nt) * 8 + 2 * q + reg;
                spart[mwg * 200 + s] = v;
            }
        }
    }
    __syncthreads();
    if (tid < 200) {
        float s4 = spart[tid] + spart[200 + tid] + spart[400 + tid] + spart[600 + tid];
        float sc3 = gr3[0] * rsqrtf(vr3[0] + EPS);
        float bi3 = br3[0] - mr3[0] * sc3;
        d_scores[n * 400 + half * 200 + tid] = siluf(sc3 * s4 + bi3);
    }
}

// ---- K4: att[n][c] = sum_s scores[n][s] * feat[b][s][c]; 2 n/block, 4 s-quarters ----
__global__ void __launch_bounds__(512, 2) k_att() {
    __shared__ float sco[2 * 400];
    __shared__ float part[4][2][128];
    int n0 = blockIdx.x * 2, b = n0 / 400, tid = threadIdx.x;
    for (int i = tid; i < 800; i += 512) sco[i] = d_scores[n0 * 400 + i];
    __syncthreads();
    int c = tid & 127, sq = tid >> 7;      // sq: 0..3
    float a0 = 0.f, a1 = 0.f;
    const float* fb = d_feat + b * 400 * 128;
    int s0 = sq * 100;
#pragma unroll 5
    for (int s = s0; s < s0 + 100; ++s) {
        float f = fb[s * 128 + c];
        a0 += sco[s] * f;
        a1 += sco[400 + s] * f;
    }
    part[sq][0][c] = a0;
    part[sq][1][c] = a1;
    __syncthreads();
    if (tid < 256) {
        int j = tid >> 7, cc = tid & 127;
        float v = part[0][j][cc] + part[1][j][cc] + part[2][j][cc] + part[3][j][cc];
        d_att[(n0 + j) * 128 + cc] = v;
    }
}

// ---- K5: out = SiLU(BN(conv1x1(att, w2))) + x ----
__global__ void k_out(float* __restrict__ out, const float* __restrict__ x,
                      const float* __restrict__ w2,
                      const float* __restrict__ g2, const float* __restrict__ b2,
                      const float* __restrict__ m2, const float* __restrict__ v2) {
    extern __shared__ float sm[];
    float* w2s  = sm;              // 128*129
    float* atts = sm + 128 * 129;  // 20*128
    int bb = blockIdx.x / 20, h = blockIdx.x % 20, tid = threadIdx.x;
    for (int idx = tid; idx < 128 * 128; idx += 512) {
        int oc = idx >> 7, ic = idx & 127;
        w2s[oc * 129 + ic] = w2[idx];
    }
    for (int idx = tid; idx < 2560; idx += 512) {
        int w = idx >> 7, ic = idx & 127;
        atts[idx] = d_att[(bb * 400 + h * 20 + w) * 128 + ic];
    }
    __syncthreads();
    int oc = tid & 127, wh = tid >> 7;   // wh: 0..3
    float sc = g2[oc] * rsqrtf(v2[oc] + EPS);
    float bi = b2[oc] - m2[oc] * sc;
    for (int w = wh * 5; w < wh * 5 + 5; ++w) {
        float acc = 0.f;
#pragma unroll 8
        for (int ic = 0; ic < 128; ++ic) acc += w2s[oc * 129 + ic] * atts[w * 128 + ic];
        float y = acc * sc + bi;
        int gi = (bb * 128 + oc) * 400 + h * 20 + w;
        out[gi] = siluf(y) + x[gi];
    }
}

extern "C" void kernel_launch(void* const* d_in, const int* in_sizes, int n_in,
                              void* d_out, int out_size) {
    const float* x   = (const float*)d_in[0];
    const float* w1  = (const float*)d_in[1];
    const float* g1  = (const float*)d_in[2];
    const float* b1  = (const float*)d_in[3];
    const float* m1  = (const float*)d_in[4];
    const float* v1  = (const float*)d_in[5];
    const float* w2  = (const float*)d_in[6];
    const float* g2  = (const float*)d_in[7];
    const float* b2  = (const float*)d_in[8];
    const float* m2  = (const float*)d_in[9];
    const float* v2  = (const float*)d_in[10];
    const float* wr1 = (const float*)d_in[11];
    const float* gr1 = (const float*)d_in[12];
    const float* br1 = (const float*)d_in[13];
    const float* mr1 = (const float*)d_in[14];
    const float* vr1 = (const float*)d_in[15];
    const float* wr2 = (const float*)d_in[16];
    const float* gr2 = (const float*)d_in[17];
    const float* br2 = (const float*)d_in[18];
    const float* mr2 = (const float*)d_in[19];
    const float* vr2 = (const float*)d_in[20];
    const float* wr3 = (const float*)d_in[21];
    const float* gr3 = (const float*)d_in[22];
    const float* br3 = (const float*)d_in[23];
    const float* mr3 = (const float*)d_in[24];
    const float* vr3 = (const float*)d_in[25];
    float* out = (float*)d_out;

    const int smem_rel  = (32 * ROWU2 * 2 + 264 + 264 + 384 + 800 + 384) * 4;
    const int smem_prep = (128 * 257 + 2 * 260) * 4;

    cudaFuncSetAttribute(k_feat, cudaFuncAttributeMaxDynamicSharedMemorySize, 76288);
    cudaFuncSetAttribute(k_prep, cudaFuncAttributeMaxDynamicSharedMemorySize, smem_prep);
    cudaFuncSetAttribute(k_rel,  cudaFuncAttributeMaxDynamicSharedMemorySize, smem_rel);
    cudaFuncSetAttribute(k_out,  cudaFuncAttributeMaxDynamicSharedMemorySize, 76288);

    k_feat<<<76, 512, 76288>>>(x, w1, g1, b1, m1, v1, wr2);    // blocks 40..75 pack wr2
    k_prep<<<200, 256, smem_prep>>>(wr1, gr1, br1, mr1, vr1);
    k_rel<<<1600, 640, smem_rel>>>(gr2, br2, mr2, vr2, wr3, gr3, br3, mr3, vr3);
    k_att<<<400, 512>>>();
    k_out<<<40, 512, 76288>>>(out, x, w2, g2, b2, m2, v2);
}